// round 16
// baseline (speedup 1.0000x reference)
#include <cuda_runtime.h>
#include <cstdint>

// Problem constants
#define BB 4
#define SS 1024
#define DD 512
#define HH 8
#define DKK 64
#define BSD (BB*SS*DD)   // 2097152
#define TQ 16            // query rows per attention CTA
#define RS2 1028         // padded score row stride
#define KBUF 4864        // 64*76 staging buffer stride (floats)

// ---------------- scratch (device globals; no allocation) ----------------
__device__ float g_bufQ[2][BSD];
__device__ float g_bufK[2][BSD];
__device__ float g_bufV[2][BSD];
__device__ float g_bufO[2][BSD];

// ---------------- tf32 helpers ----------------
__device__ __forceinline__ float cvt_tf32f(float x) {
    unsigned r;
    asm("cvt.rna.tf32.f32 %0, %1;" : "=r"(r) : "f"(x));
    return __uint_as_float(r);
}
__device__ __forceinline__ void mma_tf32(float* c,
                                         unsigned a0, unsigned a1, unsigned a2, unsigned a3,
                                         unsigned b0, unsigned b1) {
    asm("mma.sync.aligned.m16n8k8.row.col.f32.tf32.tf32.f32 "
        "{%0,%1,%2,%3}, {%4,%5,%6,%7}, {%8,%9}, {%0,%1,%2,%3};"
        : "+f"(c[0]), "+f"(c[1]), "+f"(c[2]), "+f"(c[3])
        : "r"(a0), "r"(a1), "r"(a2), "r"(a3), "r"(b0), "r"(b1));
}

// ---------------- tf32 tensor-core GEMM (unchanged) ----------------
struct GB  { const float* A; const float* W; const float* bias; float* C; };
struct GB8 { GB g[8]; };

__device__ __forceinline__ unsigned cvt_tf32(float x) {
    unsigned r;
    asm("cvt.rna.tf32.f32 %0, %1;" : "=r"(r) : "f"(x));
    return r;
}

__global__ __launch_bounds__(256)
void gemm_tc_kernel(GB8 args) {
    const GB p = args.g[blockIdx.z];

    __shared__ __align__(16) float As[128][36];
    __shared__ __align__(16) float Ws[32][136];

    const int tid  = threadIdx.x;
    const int lane = tid & 31;
    const int wid  = tid >> 5;
    const int wm0  = (wid & 1) * 64;
    const int wn0  = (wid >> 1) * 32;
    const int m0   = blockIdx.y * 128;
    const int n0   = blockIdx.x * 128;

    const int am = tid >> 3;
    const int ak = (tid & 7) * 4;
    const int wk = tid >> 5;
    const int wn = (tid & 31) * 4;

    const float* Ap = p.A + (size_t)(m0 + am) * 512 + ak;
    const float* Wp = p.W + (size_t)wk * 512 + n0 + wn;

    float4 aR[4], wR[4];
    #pragma unroll
    for (int r = 0; r < 4; r++) {
        aR[r] = *(const float4*)(Ap + (size_t)(r * 32) * 512);
        wR[r] = *(const float4*)(Wp + (size_t)(r * 8) * 512);
    }

    float acc[4][4][4];
    #pragma unroll
    for (int i = 0; i < 4; i++)
        #pragma unroll
        for (int j = 0; j < 4; j++)
            #pragma unroll
            for (int u = 0; u < 4; u++) acc[i][j][u] = 0.f;

    for (int kt = 0; kt < 16; kt++) {
        #pragma unroll
        for (int r = 0; r < 4; r++) {
            float4 a = aR[r];
            a.x = __uint_as_float(cvt_tf32(a.x));
            a.y = __uint_as_float(cvt_tf32(a.y));
            a.z = __uint_as_float(cvt_tf32(a.z));
            a.w = __uint_as_float(cvt_tf32(a.w));
            *(float4*)&As[am + r * 32][ak] = a;
            float4 w = wR[r];
            w.x = __uint_as_float(cvt_tf32(w.x));
            w.y = __uint_as_float(cvt_tf32(w.y));
            w.z = __uint_as_float(cvt_tf32(w.z));
            w.w = __uint_as_float(cvt_tf32(w.w));
            *(float4*)&Ws[wk + r * 8][wn] = w;
        }
        __syncthreads();

        if (kt < 15) {
            const int ko = (kt + 1) * 32;
            #pragma unroll
            for (int r = 0; r < 4; r++) {
                aR[r] = *(const float4*)(Ap + (size_t)(r * 32) * 512 + ko);
                wR[r] = *(const float4*)(Wp + (size_t)(r * 8) * 512 + (size_t)ko * 512);
            }
        }

        #pragma unroll
        for (int ks = 0; ks < 4; ks++) {
            const int kk = ks * 8 + (lane & 3);
            unsigned b0[4], b1[4];
            #pragma unroll
            for (int tn = 0; tn < 4; tn++) {
                int n = wn0 + tn * 8 + (lane >> 2);
                b0[tn] = __float_as_uint(Ws[kk][n]);
                b1[tn] = __float_as_uint(Ws[kk + 4][n]);
            }
            #pragma unroll
            for (int tm = 0; tm < 4; tm++) {
                int m = wm0 + tm * 16 + (lane >> 2);
                unsigned a0 = __float_as_uint(As[m][kk]);
                unsigned a1 = __float_as_uint(As[m + 8][kk]);
                unsigned a2 = __float_as_uint(As[m][kk + 4]);
                unsigned a3 = __float_as_uint(As[m + 8][kk + 4]);
                #pragma unroll
                for (int tn = 0; tn < 4; tn++)
                    mma_tf32(acc[tm][tn], a0, a1, a2, a3, b0[tn], b1[tn]);
            }
        }
        __syncthreads();
    }

    const int cm = lane >> 2;
    const int cn = (lane & 3) * 2;
    #pragma unroll
    for (int tn = 0; tn < 4; tn++) {
        int n = n0 + wn0 + tn * 8 + cn;
        float2 bb = *(const float2*)(p.bias + n);
        #pragma unroll
        for (int tm = 0; tm < 4; tm++) {
            int m = m0 + wm0 + tm * 16 + cm;
            float2 o0, o1;
            o0.x = acc[tm][tn][0] + bb.x; o0.y = acc[tm][tn][1] + bb.y;
            o1.x = acc[tm][tn][2] + bb.x; o1.y = acc[tm][tn][3] + bb.y;
            *(float2*)(p.C + (size_t)m * 512 + n) = o0;
            *(float2*)(p.C + (size_t)(m + 8) * 512 + n) = o1;
        }
    }
}

// ---------------- attention (tensor-core, split-tf32, double-buffered) ----------------
__device__ __forceinline__ float warpReduceSum(float v) {
    #pragma unroll
    for (int o = 16; o > 0; o >>= 1) v += __shfl_xor_sync(0xffffffffu, v, o);
    return v;
}
__device__ __forceinline__ float warpReduceMax(float v) {
    #pragma unroll
    for (int o = 16; o > 0; o >>= 1) v = fmaxf(v, __shfl_xor_sync(0xffffffffu, v, o));
    return v;
}

// dynamic smem layout (floats)
#define OFF_KH 16448                    // s_sc = 16*1028
#define OFF_QL (OFF_KH + 2*KBUF)        // Q-lo staging only (16 rows)
#define OFF_RS (OFF_QL + 16*76)
#define ATTN_SM_FLOATS (OFF_RS + 16)    // 27408 floats = 109632 B -> 2 CTA/SM

__global__ __launch_bounds__(256, 2)
void attn_kernel(const float* __restrict__ gammas) {
    extern __shared__ float sm[];
    float* s_sc = sm;                   // [16][1028]
    float* s_kh = sm + OFF_KH;          // [2][64][76]  (Q-hi staging, then K-hi/V-hi ping-pong)
    float* s_ql = sm + OFF_QL;          // [16][76]  (Q-lo staging)
    float* s_rs = sm + OFF_RS;          // [16]

    // heavy-first (LPT) ordering: largest q-tiles issue first
    const int q0 = (int)(gridDim.y - 1 - blockIdx.y) * TQ;
    const int bh = blockIdx.x;
    const int b  = bh >> 3;
    const int h  = bh & 7;
    const int st = blockIdx.z;

    const int tid  = threadIdx.x;
    const int lane = tid & 31;
    const int w    = tid >> 5;          // warp 0..7
    const int fr   = lane >> 2;         // fragment row 0..7
    const int fc   = lane & 3;          // fragment col 0..3

    const float* __restrict__ Qbase = g_bufQ[st] + ((size_t)(b * SS + q0)) * DD + h * DKK;
    const float* __restrict__ Kbase = g_bufK[st] + (size_t)b * SS * DD + h * DKK;
    const float* __restrict__ Vbase = g_bufV[st] + (size_t)b * SS * DD + h * DKK;

    // ---- stage Q (16x64) as tf32 hi/lo (hi through staging buffer 0) ----
    {
        int r = tid >> 4, qd = (tid & 15) * 4;
        float4 q = *(const float4*)(Qbase + (size_t)r * DD + qd);
        float4 hi, lo;
        hi.x = cvt_tf32f(q.x); lo.x = cvt_tf32f(q.x - hi.x);
        hi.y = cvt_tf32f(q.y); lo.y = cvt_tf32f(q.y - hi.y);
        hi.z = cvt_tf32f(q.z); lo.z = cvt_tf32f(q.z - hi.z);
        hi.w = cvt_tf32f(q.w); lo.w = cvt_tf32f(q.w - hi.w);
        *(float4*)&s_kh[r * 76 + qd] = hi;
        *(float4*)&s_ql[r * 76 + qd] = lo;
    }
    __syncthreads();

    // ---- cache Q fragments in registers ----
    unsigned qfh[8][4], qfl[8][4];
    #pragma unroll
    for (int kt = 0; kt < 8; kt++) {
        int kk = kt * 8 + fc;
        qfh[kt][0] = __float_as_uint(s_kh[fr * 76 + kk]);
        qfh[kt][1] = __float_as_uint(s_kh[(fr + 8) * 76 + kk]);
        qfh[kt][2] = __float_as_uint(s_kh[fr * 76 + kk + 4]);
        qfh[kt][3] = __float_as_uint(s_kh[(fr + 8) * 76 + kk + 4]);
        qfl[kt][0] = __float_as_uint(s_ql[fr * 76 + kk]);
        qfl[kt][1] = __float_as_uint(s_ql[(fr + 8) * 76 + kk]);
        qfl[kt][2] = __float_as_uint(s_ql[fr * 76 + kk + 4]);
        qfl[kt][3] = __float_as_uint(s_ql[(fr + 8) * 76 + kk + 4]);
    }
    __syncthreads();                    // Q staging done; s_kh free for K

    const int Lmax = q0 + TQ;
    const int nch  = (Lmax + 63) >> 6;

    const int lr = tid >> 4;             // loader row 0..15
    const int lq = (tid & 15) * 4;       // loader col quad

    // ---------- Phase 1: S = Q @ K^T (K-hi; ping-pong staging, 1 sync/chunk) ----------
    {
        float4 kreg[4];
        #pragma unroll
        for (int i = 0; i < 4; i++)
            kreg[i] = *(const float4*)(Kbase + (size_t)(lr + i * 16) * DD + lq);
        #pragma unroll
        for (int i = 0; i < 4; i++) {
            int row = lr + i * 16;
            float4 k = kreg[i];
            float4 hi;
            hi.x = cvt_tf32f(k.x); hi.y = cvt_tf32f(k.y);
            hi.z = cvt_tf32f(k.z); hi.w = cvt_tf32f(k.w);
            *(float4*)&s_kh[row * 76 + lq] = hi;     // buffer 0
        }
        __syncthreads();

        for (int c = 0; c < nch; c++) {
            const float* kb = s_kh + (c & 1) * KBUF;

            if (c + 1 < nch) {
                #pragma unroll
                for (int i = 0; i < 4; i++)
                    kreg[i] = *(const float4*)(Kbase +
                        (size_t)((c + 1) * 64 + lr + i * 16) * DD + lq);
            }

            float cc0[4] = {0.f, 0.f, 0.f, 0.f};   // qhi*khi
            float cc2[4] = {0.f, 0.f, 0.f, 0.f};   // qlo*khi
            const int nb = w * 8;            // this warp's 8 keys within chunk
            #pragma unroll
            for (int kt = 0; kt < 8; kt++) {
                int kk = kt * 8 + fc;
                int ja = (nb + fr) * 76;
                unsigned bh0 = __float_as_uint(kb[ja + kk]);
                unsigned bh1 = __float_as_uint(kb[ja + kk + 4]);
                mma_tf32(cc0, qfh[kt][0], qfh[kt][1], qfh[kt][2], qfh[kt][3], bh0, bh1);
                mma_tf32(cc2, qfl[kt][0], qfl[kt][1], qfl[kt][2], qfl[kt][3], bh0, bh1);
            }
            int jcol = c * 64 + nb + fc * 2;
            float2 s0, s1;
            s0.x = (cc0[0] + cc2[0]) * 0.125f;
            s0.y = (cc0[1] + cc2[1]) * 0.125f;
            s1.x = (cc0[2] + cc2[2]) * 0.125f;
            s1.y = (cc0[3] + cc2[3]) * 0.125f;
            *(float2*)&s_sc[fr * RS2 + jcol] = s0;
            *(float2*)&s_sc[(fr + 8) * RS2 + jcol] = s1;

            if (c + 1 < nch) {
                float* kb2 = s_kh + ((c + 1) & 1) * KBUF;
                #pragma unroll
                for (int i = 0; i < 4; i++) {
                    int row = lr + i * 16;
                    float4 k = kreg[i];
                    float4 hi;
                    hi.x = cvt_tf32f(k.x); hi.y = cvt_tf32f(k.y);
                    hi.z = cvt_tf32f(k.z); hi.w = cvt_tf32f(k.w);
                    *(float4*)&kb2[row * 76 + lq] = hi;
                }
            }
            __syncthreads();
        }
    }

    // ---------- Phase 2: per-row softmax / cumsum / decay / softmax ----------
    const float gh = gammas[h];
    const float gv = -log1pf(__expf(gh));
    const int jz = nch * 64;             // columns phase 3 will read
    #pragma unroll
    for (int rr = 0; rr < 2; rr++) {
        int rloc = w + rr * 8;
        float* row = s_sc + rloc * RS2;
        const int rl = q0 + rloc;
        const int Lr = rl + 1;

        float m1 = -3.0e38f;
        #pragma unroll
        for (int i = 0; i < 32; i++) {
            if (i * 32 >= Lr) break;
            int j = i * 32 + lane;
            if (j < Lr) m1 = fmaxf(m1, row[j]);
        }
        m1 = warpReduceMax(m1);

        float c_reg[32];
        float tot;
        {
            float carry = 0.f;
            #pragma unroll
            for (int i = 0; i < 32; i++) {
                if (i * 32 >= Lr) break;
                int j = i * 32 + lane;
                float x = (j < Lr) ? __expf(row[j] - m1) : 0.f;
                #pragma unroll
                for (int d = 1; d < 32; d <<= 1) {
                    float y = __shfl_up_sync(0xffffffffu, x, d);
                    if (lane >= d) x += y;
                }
                c_reg[i] = carry + x;
                carry += __shfl_sync(0xffffffffu, x, 31);
            }
            tot = carry;
        }

        const float rtot = 1.0f / tot;
        float m2 = -3.0e38f;
        #pragma unroll
        for (int i = 0; i < 32; i++) {
            if (i * 32 >= Lr) break;
            int j = i * 32 + lane;
            if (j < Lr) {
                float s = row[j];
                float rem = fmaxf((tot - c_reg[i]) * rtot, 0.f);
                float dist = sqrtf(rem * (float)(rl - j));
                float em = fminf(fmaxf(__expf(dist * gv), 1e-5f), 1e5f);
                float v = s * em;
                row[j] = v;
                m2 = fmaxf(m2, v);
            }
        }
        m2 = warpReduceMax(m2);

        float psum = 0.f;
        #pragma unroll
        for (int i = 0; i < 32; i++) {
            if (i * 32 >= jz) break;
            int j = i * 32 + lane;
            float e = 0.f;
            if (j < Lr) {
                e = __expf(row[j] - m2);
                psum += e;
            }
            row[j] = e;                  // zero beyond Lr up to jz for phase 3
        }
        psum = warpReduceSum(psum);
        if (lane == 0) s_rs[rloc] = 1.0f / psum;
    }
    __syncthreads();

    // ---------- Phase 3: O = P @ V (P tf32-hi, V tf32-hi; ping-pong staging) ----------
    float oc0[4] = {0.f, 0.f, 0.f, 0.f};
    const int vb = w * 8 + fr;           // this warp's d-column (n index)
    {
        float4 vreg[4];
        #pragma unroll
        for (int i = 0; i < 4; i++)
            vreg[i] = *(const float4*)(Vbase + (size_t)(lr + i * 16) * DD + lq);
        #pragma unroll
        for (int i = 0; i < 4; i++) {
            int row = lr + i * 16;
            float4 v = vreg[i];
            float4 hi;
            hi.x = cvt_tf32f(v.x); hi.y = cvt_tf32f(v.y);
            hi.z = cvt_tf32f(v.z); hi.w = cvt_tf32f(v.w);
            *(float4*)&s_kh[row * 76 + lq] = hi;     // buffer 0
        }
        __syncthreads();

        for (int c = 0; c < nch; c++) {
            const float* vbuf = s_kh + (c & 1) * KBUF;

            if (c + 1 < nch) {
                #pragma unroll
                for (int i = 0; i < 4; i++)
                    vreg[i] = *(const float4*)(Vbase +
                        (size_t)((c + 1) * 64 + lr + i * 16) * DD + lq);
            }

            #pragma unroll
            for (int kt = 0; kt < 8; kt++) {
                int kcol = c * 64 + kt * 8 + fc;
                float h0 = cvt_tf32f(s_sc[fr * RS2 + kcol]);
                float h1 = cvt_tf32f(s_sc[(fr + 8) * RS2 + kcol]);
                float h2 = cvt_tf32f(s_sc[fr * RS2 + kcol + 4]);
                float h3 = cvt_tf32f(s_sc[(fr + 8) * RS2 + kcol + 4]);

                int ka = (kt * 8 + fc) * 76;
                unsigned bh0 = __float_as_uint(vbuf[ka + vb]);
                unsigned bh1 = __float_as_uint(vbuf[ka + 4 * 76 + vb]);

                mma_tf32(oc0, __float_as_uint(h0), __float_as_uint(h1),
                              __float_as_uint(h2), __float_as_uint(h3), bh0, bh1);
            }

            if (c + 1 < nch) {
                float* vb2 = s_kh + ((c + 1) & 1) * KBUF;
                #pragma unroll
                for (int i = 0; i < 4; i++) {
                    int row = lr + i * 16;
                    float4 v = vreg[i];
                    float4 hi;
                    hi.x = cvt_tf32f(v.x); hi.y = cvt_tf32f(v.y);
                    hi.z = cvt_tf32f(v.z); hi.w = cvt_tf32f(v.w);
                    *(float4*)&vb2[row * 76 + lq] = hi;
                }
            }
            __syncthreads();
        }
    }

    // epilogue: scale by 1/sum, write out
    float* Obase = g_bufO[st] + ((size_t)(b * SS + q0)) * DD + h * DKK;
    float rs0 = s_rs[fr], rs1 = s_rs[fr + 8];
    int dcol = w * 8 + fc * 2;
    float2 o0, o1;
    o0.x = oc0[0] * rs0; o0.y = oc0[1] * rs0;
    o1.x = oc0[2] * rs1; o1.y = oc0[3] * rs1;
    *(float2*)(Obase + (size_t)fr * DD + dcol) = o0;
    *(float2*)(Obase + (size_t)(fr + 8) * DD + dcol) = o1;
}

// ---------------- launch ----------------
extern "C" void kernel_launch(void* const* d_in, const int* in_sizes, int n_in,
                              void* d_out, int out_size) {
    const float* q_m  = (const float*)d_in[0];
    const float* q_c  = (const float*)d_in[1];
    const float* k_m  = (const float*)d_in[2];
    const float* k_c  = (const float*)d_in[3];
    const float* v_m  = (const float*)d_in[4];
    const float* v_c  = (const float*)d_in[5];
    const float* Wk_m = (const float*)d_in[6];
    const float* bk_m = (const float*)d_in[7];
    const float* Wk_c = (const float*)d_in[8];
    const float* bk_c = (const float*)d_in[9];
    const float* Wv_m = (const float*)d_in[10];
    const float* bv_m = (const float*)d_in[11];
    const float* Wv_c = (const float*)d_in[12];
    const float* bv_c = (const float*)d_in[13];
    const float* Wo_m = (const float*)d_in[14];
    const float* bo_m = (const float*)d_in[15];
    const float* Wo_c = (const float*)d_in[16];
    const float* bo_c = (const float*)d_in[17];
    const float* gam  = (const float*)d_in[18];
    float* out = (float*)d_out;

    float *bQ, *bK, *bV, *bO;
    cudaGetSymbolAddress((void**)&bQ, g_bufQ);
    cudaGetSymbolAddress((void**)&bK, g_bufK);
    cudaGetSymbolAddress((void**)&bV, g_bufV);
    cudaGetSymbolAddress((void**)&bO, g_bufO);

    cudaFuncSetAttribute(attn_kernel, cudaFuncAttributeMaxDynamicSharedMemorySize,
                         ATTN_SM_FLOATS * 4);

    // 6 projection GEMMs in one launch (Q and K share Wk per stream)
    GB8 proj{};
    proj.g[0] = { q_m, Wk_m, bk_m, bQ };
    proj.g[1] = { k_m, Wk_m, bk_m, bK };
    proj.g[2] = { v_m, Wv_m, bv_m, bV };
    proj.g[3] = { q_c, Wk_c, bk_c, bQ + BSD };
    proj.g[4] = { k_c, Wk_c, bk_c, bK + BSD };
    proj.g[5] = { v_c, Wv_c, bv_c, bV + BSD };
    gemm_tc_kernel<<<dim3(512 / 128, 4096 / 128, 6), 256>>>(proj);

    // attention (both streams) — heavy-first tile order
    attn_kernel<<<dim3(BB * HH, SS / TQ, 2), 256, ATTN_SM_FLOATS * 4>>>(gam);

    // 2 output GEMMs in one launch
    GB8 outp{};
    outp.g[0] = { bO,       Wo_m, bo_m, out };
    outp.g[1] = { bO + BSD, Wo_c, bo_c, out + BSD };
    gemm_tc_kernel<<<dim3(512 / 128, 4096 / 128, 2), 256>>>(outp);
}

// round 17
// speedup vs baseline: 1.0201x; 1.0201x over previous
#include <cuda_runtime.h>
#include <cstdint>

// Problem constants
#define BB 4
#define SS 1024
#define DD 512
#define HH 8
#define DKK 64
#define BSD (BB*SS*DD)   // 2097152
#define TQ 32            // query rows per attention CTA
#define RS2 1028         // padded score row stride

// ---------------- scratch (device globals; no allocation) ----------------
__device__ float g_bufQ[2][BSD];
__device__ float g_bufK[2][BSD];
__device__ float g_bufV[2][BSD];
__device__ float g_bufO[2][BSD];

// ---------------- tf32 helpers ----------------
__device__ __forceinline__ float cvt_tf32f(float x) {
    unsigned r;
    asm("cvt.rna.tf32.f32 %0, %1;" : "=r"(r) : "f"(x));
    return __uint_as_float(r);
}
__device__ __forceinline__ void mma_tf32(float* c,
                                         unsigned a0, unsigned a1, unsigned a2, unsigned a3,
                                         unsigned b0, unsigned b1) {
    asm("mma.sync.aligned.m16n8k8.row.col.f32.tf32.tf32.f32 "
        "{%0,%1,%2,%3}, {%4,%5,%6,%7}, {%8,%9}, {%0,%1,%2,%3};"
        : "+f"(c[0]), "+f"(c[1]), "+f"(c[2]), "+f"(c[3])
        : "r"(a0), "r"(a1), "r"(a2), "r"(a3), "r"(b0), "r"(b1));
}

// ---------------- tf32 tensor-core GEMM (unchanged) ----------------
struct GB  { const float* A; const float* W; const float* bias; float* C; };
struct GB8 { GB g[8]; };

__device__ __forceinline__ unsigned cvt_tf32(float x) {
    unsigned r;
    asm("cvt.rna.tf32.f32 %0, %1;" : "=r"(r) : "f"(x));
    return r;
}

__global__ __launch_bounds__(256)
void gemm_tc_kernel(GB8 args) {
    const GB p = args.g[blockIdx.z];

    __shared__ __align__(16) float As[128][36];
    __shared__ __align__(16) float Ws[32][136];

    const int tid  = threadIdx.x;
    const int lane = tid & 31;
    const int wid  = tid >> 5;
    const int wm0  = (wid & 1) * 64;
    const int wn0  = (wid >> 1) * 32;
    const int m0   = blockIdx.y * 128;
    const int n0   = blockIdx.x * 128;

    const int am = tid >> 3;
    const int ak = (tid & 7) * 4;
    const int wk = tid >> 5;
    const int wn = (tid & 31) * 4;

    const float* Ap = p.A + (size_t)(m0 + am) * 512 + ak;
    const float* Wp = p.W + (size_t)wk * 512 + n0 + wn;

    float4 aR[4], wR[4];
    #pragma unroll
    for (int r = 0; r < 4; r++) {
        aR[r] = *(const float4*)(Ap + (size_t)(r * 32) * 512);
        wR[r] = *(const float4*)(Wp + (size_t)(r * 8) * 512);
    }

    float acc[4][4][4];
    #pragma unroll
    for (int i = 0; i < 4; i++)
        #pragma unroll
        for (int j = 0; j < 4; j++)
            #pragma unroll
            for (int u = 0; u < 4; u++) acc[i][j][u] = 0.f;

    for (int kt = 0; kt < 16; kt++) {
        #pragma unroll
        for (int r = 0; r < 4; r++) {
            float4 a = aR[r];
            a.x = __uint_as_float(cvt_tf32(a.x));
            a.y = __uint_as_float(cvt_tf32(a.y));
            a.z = __uint_as_float(cvt_tf32(a.z));
            a.w = __uint_as_float(cvt_tf32(a.w));
            *(float4*)&As[am + r * 32][ak] = a;
            float4 w = wR[r];
            w.x = __uint_as_float(cvt_tf32(w.x));
            w.y = __uint_as_float(cvt_tf32(w.y));
            w.z = __uint_as_float(cvt_tf32(w.z));
            w.w = __uint_as_float(cvt_tf32(w.w));
            *(float4*)&Ws[wk + r * 8][wn] = w;
        }
        __syncthreads();

        if (kt < 15) {
            const int ko = (kt + 1) * 32;
            #pragma unroll
            for (int r = 0; r < 4; r++) {
                aR[r] = *(const float4*)(Ap + (size_t)(r * 32) * 512 + ko);
                wR[r] = *(const float4*)(Wp + (size_t)(r * 8) * 512 + (size_t)ko * 512);
            }
        }

        #pragma unroll
        for (int ks = 0; ks < 4; ks++) {
            const int kk = ks * 8 + (lane & 3);
            unsigned b0[4], b1[4];
            #pragma unroll
            for (int tn = 0; tn < 4; tn++) {
                int n = wn0 + tn * 8 + (lane >> 2);
                b0[tn] = __float_as_uint(Ws[kk][n]);
                b1[tn] = __float_as_uint(Ws[kk + 4][n]);
            }
            #pragma unroll
            for (int tm = 0; tm < 4; tm++) {
                int m = wm0 + tm * 16 + (lane >> 2);
                unsigned a0 = __float_as_uint(As[m][kk]);
                unsigned a1 = __float_as_uint(As[m + 8][kk]);
                unsigned a2 = __float_as_uint(As[m][kk + 4]);
                unsigned a3 = __float_as_uint(As[m + 8][kk + 4]);
                #pragma unroll
                for (int tn = 0; tn < 4; tn++)
                    mma_tf32(acc[tm][tn], a0, a1, a2, a3, b0[tn], b1[tn]);
            }
        }
        __syncthreads();
    }

    const int cm = lane >> 2;
    const int cn = (lane & 3) * 2;
    #pragma unroll
    for (int tn = 0; tn < 4; tn++) {
        int n = n0 + wn0 + tn * 8 + cn;
        float2 bb = *(const float2*)(p.bias + n);
        #pragma unroll
        for (int tm = 0; tm < 4; tm++) {
            int m = m0 + wm0 + tm * 16 + cm;
            float2 o0, o1;
            o0.x = acc[tm][tn][0] + bb.x; o0.y = acc[tm][tn][1] + bb.y;
            o1.x = acc[tm][tn][2] + bb.x; o1.y = acc[tm][tn][3] + bb.y;
            *(float2*)(p.C + (size_t)m * 512 + n) = o0;
            *(float2*)(p.C + (size_t)(m + 8) * 512 + n) = o1;
        }
    }
}

// ---------------- attention (tensor-core, split-tf32, TQ=32, 512 threads) ----------------
__device__ __forceinline__ float warpReduceSum(float v) {
    #pragma unroll
    for (int o = 16; o > 0; o >>= 1) v += __shfl_xor_sync(0xffffffffu, v, o);
    return v;
}
__device__ __forceinline__ float warpReduceMax(float v) {
    #pragma unroll
    for (int o = 16; o > 0; o >>= 1) v = fmaxf(v, __shfl_xor_sync(0xffffffffu, v, o));
    return v;
}

// dynamic smem layout (floats)
#define OFF_KH 32896                    // s_sc = 32*1028
#define OFF_QL (OFF_KH + 64*76)         // Q-lo staging (32 rows)
#define OFF_RS (OFF_QL + 32*76)
#define ATTN_SM_FLOATS (OFF_RS + 32)    // 40224 floats = 160896 B -> 1 CTA/SM, 16 warps

__global__ __launch_bounds__(512, 1)
void attn_kernel(const float* __restrict__ gammas) {
    extern __shared__ float sm[];
    float* s_sc = sm;                   // [32][1028]
    float* s_kh = sm + OFF_KH;          // [64][76]  (Q-hi staging, then K-hi/V-hi)
    float* s_ql = sm + OFF_QL;          // [32][76]  (Q-lo staging)
    float* s_rs = sm + OFF_RS;          // [32]

    // heavy-first (LPT) ordering: largest q-tiles issue first
    const int q0 = (int)(gridDim.y - 1 - blockIdx.y) * TQ;
    const int bh = blockIdx.x;
    const int b  = bh >> 3;
    const int h  = bh & 7;
    const int st = blockIdx.z;

    const int tid  = threadIdx.x;
    const int lane = tid & 31;
    const int w    = tid >> 5;          // warp 0..15
    const int wh   = w & 7;             // warp within row-half
    const int hf   = w >> 3;            // row-half 0/1 (rows hf*16 .. hf*16+15)
    const int fr   = lane >> 2;         // fragment row 0..7
    const int fc   = lane & 3;          // fragment col 0..3

    const float* __restrict__ Qbase = g_bufQ[st] + ((size_t)(b * SS + q0)) * DD + h * DKK;
    const float* __restrict__ Kbase = g_bufK[st] + (size_t)b * SS * DD + h * DKK;
    const float* __restrict__ Vbase = g_bufV[st] + (size_t)b * SS * DD + h * DKK;

    // ---- stage Q (32x64) as tf32 hi/lo (hi through K staging buffer) ----
    {
        int r = tid >> 4, qd = (tid & 15) * 4;    // 32 rows x 16 quads = 512 threads
        float4 q = *(const float4*)(Qbase + (size_t)r * DD + qd);
        float4 hi, lo;
        hi.x = cvt_tf32f(q.x); lo.x = cvt_tf32f(q.x - hi.x);
        hi.y = cvt_tf32f(q.y); lo.y = cvt_tf32f(q.y - hi.y);
        hi.z = cvt_tf32f(q.z); lo.z = cvt_tf32f(q.z - hi.z);
        hi.w = cvt_tf32f(q.w); lo.w = cvt_tf32f(q.w - hi.w);
        *(float4*)&s_kh[r * 76 + qd] = hi;
        *(float4*)&s_ql[r * 76 + qd] = lo;
    }
    __syncthreads();

    // ---- cache this warp's Q fragments (row-half hf) in registers ----
    const int qr0 = hf * 16 + fr;
    const int qr1 = qr0 + 8;
    unsigned qfh[8][4], qfl[8][4];
    #pragma unroll
    for (int kt = 0; kt < 8; kt++) {
        int kk = kt * 8 + fc;
        qfh[kt][0] = __float_as_uint(s_kh[qr0 * 76 + kk]);
        qfh[kt][1] = __float_as_uint(s_kh[qr1 * 76 + kk]);
        qfh[kt][2] = __float_as_uint(s_kh[qr0 * 76 + kk + 4]);
        qfh[kt][3] = __float_as_uint(s_kh[qr1 * 76 + kk + 4]);
        qfl[kt][0] = __float_as_uint(s_ql[qr0 * 76 + kk]);
        qfl[kt][1] = __float_as_uint(s_ql[qr1 * 76 + kk]);
        qfl[kt][2] = __float_as_uint(s_ql[qr0 * 76 + kk + 4]);
        qfl[kt][3] = __float_as_uint(s_ql[qr1 * 76 + kk + 4]);
    }
    __syncthreads();                    // Q staging done; s_kh free for K

    const int Lmax = q0 + TQ;
    const int nch  = (Lmax + 63) >> 6;

    const int lr = tid >> 4;             // loader row 0..31 (also +32)
    const int lq = (tid & 15) * 4;       // loader col quad

    // ---------- Phase 1: S = Q @ K^T (K-hi; prefetched; shared across halves) ----------
    {
        float4 kreg[2];
        kreg[0] = *(const float4*)(Kbase + (size_t)lr * DD + lq);
        kreg[1] = *(const float4*)(Kbase + (size_t)(lr + 32) * DD + lq);

        for (int c = 0; c < nch; c++) {
            #pragma unroll
            for (int i = 0; i < 2; i++) {
                int row = lr + i * 32;
                float4 k = kreg[i];
                float4 hi;
                hi.x = cvt_tf32f(k.x); hi.y = cvt_tf32f(k.y);
                hi.z = cvt_tf32f(k.z); hi.w = cvt_tf32f(k.w);
                *(float4*)&s_kh[row * 76 + lq] = hi;
            }
            __syncthreads();

            if (c + 1 < nch) {
                kreg[0] = *(const float4*)(Kbase + (size_t)((c + 1) * 64 + lr) * DD + lq);
                kreg[1] = *(const float4*)(Kbase + (size_t)((c + 1) * 64 + lr + 32) * DD + lq);
            }

            float cc0[4] = {0.f, 0.f, 0.f, 0.f};   // qhi*khi
            float cc2[4] = {0.f, 0.f, 0.f, 0.f};   // qlo*khi
            const int nb = wh * 8;           // this warp's 8 keys within chunk
            #pragma unroll
            for (int kt = 0; kt < 8; kt++) {
                int kk = kt * 8 + fc;
                int ja = (nb + fr) * 76;
                unsigned bh0 = __float_as_uint(s_kh[ja + kk]);
                unsigned bh1 = __float_as_uint(s_kh[ja + kk + 4]);
                mma_tf32(cc0, qfh[kt][0], qfh[kt][1], qfh[kt][2], qfh[kt][3], bh0, bh1);
                mma_tf32(cc2, qfl[kt][0], qfl[kt][1], qfl[kt][2], qfl[kt][3], bh0, bh1);
            }
            int jcol = c * 64 + nb + fc * 2;
            float2 s0, s1;
            s0.x = (cc0[0] + cc2[0]) * 0.125f;
            s0.y = (cc0[1] + cc2[1]) * 0.125f;
            s1.x = (cc0[2] + cc2[2]) * 0.125f;
            s1.y = (cc0[3] + cc2[3]) * 0.125f;
            *(float2*)&s_sc[qr0 * RS2 + jcol] = s0;
            *(float2*)&s_sc[qr1 * RS2 + jcol] = s1;
            __syncthreads();
        }
    }

    // ---------- Phase 2: per-row softmax / cumsum / decay / softmax ----------
    const float gh = gammas[h];
    const float gv = -log1pf(__expf(gh));
    const int jz = nch * 64;             // columns phase 3 will read
    #pragma unroll
    for (int rr = 0; rr < 2; rr++) {
        int rloc = w + rr * 16;
        float* row = s_sc + rloc * RS2;
        const int rl = q0 + rloc;
        const int Lr = rl + 1;

        float m1 = -3.0e38f;
        #pragma unroll
        for (int i = 0; i < 32; i++) {
            if (i * 32 >= Lr) break;
            int j = i * 32 + lane;
            if (j < Lr) m1 = fmaxf(m1, row[j]);
        }
        m1 = warpReduceMax(m1);

        float c_reg[32];
        float tot;
        {
            float carry = 0.f;
            #pragma unroll
            for (int i = 0; i < 32; i++) {
                if (i * 32 >= Lr) break;
                int j = i * 32 + lane;
                float x = (j < Lr) ? __expf(row[j] - m1) : 0.f;
                #pragma unroll
                for (int d = 1; d < 32; d <<= 1) {
                    float y = __shfl_up_sync(0xffffffffu, x, d);
                    if (lane >= d) x += y;
                }
                c_reg[i] = carry + x;
                carry += __shfl_sync(0xffffffffu, x, 31);
            }
            tot = carry;
        }

        const float rtot = 1.0f / tot;
        float m2 = -3.0e38f;
        #pragma unroll
        for (int i = 0; i < 32; i++) {
            if (i * 32 >= Lr) break;
            int j = i * 32 + lane;
            if (j < Lr) {
                float s = row[j];
                float rem = fmaxf((tot - c_reg[i]) * rtot, 0.f);
                float dist = sqrtf(rem * (float)(rl - j));
                float em = fminf(fmaxf(__expf(dist * gv), 1e-5f), 1e5f);
                float v = s * em;
                row[j] = v;
                m2 = fmaxf(m2, v);
            }
        }
        m2 = warpReduceMax(m2);

        float psum = 0.f;
        #pragma unroll
        for (int i = 0; i < 32; i++) {
            if (i * 32 >= jz) break;
            int j = i * 32 + lane;
            float e = 0.f;
            if (j < Lr) {
                e = __expf(row[j] - m2);
                psum += e;
            }
            row[j] = e;                  // zero beyond Lr up to jz for phase 3
        }
        psum = warpReduceSum(psum);
        if (lane == 0) s_rs[rloc] = 1.0f / psum;
    }
    __syncthreads();

    // ---------- Phase 3: O = P @ V (P tf32-hi, V tf32-hi; prefetched; shared chunk) ----------
    float oc0[4] = {0.f, 0.f, 0.f, 0.f};
    const int vb = wh * 8 + fr;          // this warp's d-column (n index)
    {
        float4 vreg[2];
        vreg[0] = *(const float4*)(Vbase + (size_t)lr * DD + lq);
        vreg[1] = *(const float4*)(Vbase + (size_t)(lr + 32) * DD + lq);

        for (int c = 0; c < nch; c++) {
            #pragma unroll
            for (int i = 0; i < 2; i++) {
                int row = lr + i * 32;
                float4 v = vreg[i];
                float4 hi;
                hi.x = cvt_tf32f(v.x); hi.y = cvt_tf32f(v.y);
                hi.z = cvt_tf32f(v.z); hi.w = cvt_tf32f(v.w);
                *(float4*)&s_kh[row * 76 + lq] = hi;
            }
            __syncthreads();

            if (c + 1 < nch) {
                vreg[0] = *(const float4*)(Vbase + (size_t)((c + 1) * 64 + lr) * DD + lq);
                vreg[1] = *(const float4*)(Vbase + (size_t)((c + 1) * 64 + lr + 32) * DD + lq);
            }

            #pragma unroll
            for (int kt = 0; kt < 8; kt++) {
                int kcol = c * 64 + kt * 8 + fc;
                float h0 = cvt_tf32f(s_sc[qr0 * RS2 + kcol]);
                float h1 = cvt_tf32f(s_sc[qr1 * RS2 + kcol]);
                float h2 = cvt_tf32f(s_sc[qr0 * RS2 + kcol + 4]);
                float h3 = cvt_tf32f(s_sc[qr1 * RS2 + kcol + 4]);

                int ka = (kt * 8 + fc) * 76;
                unsigned bh0 = __float_as_uint(s_kh[ka + vb]);
                unsigned bh1 = __float_as_uint(s_kh[ka + 4 * 76 + vb]);

                mma_tf32(oc0, __float_as_uint(h0), __float_as_uint(h1),
                              __float_as_uint(h2), __float_as_uint(h3), bh0, bh1);
            }
            __syncthreads();
        }
    }

    // epilogue: scale by 1/sum, write out
    float* Obase = g_bufO[st] + ((size_t)(b * SS + q0)) * DD + h * DKK;
    float rs0 = s_rs[qr0], rs1 = s_rs[qr1];
    int dcol = wh * 8 + fc * 2;
    float2 o0, o1;
    o0.x = oc0[0] * rs0; o0.y = oc0[1] * rs0;
    o1.x = oc0[2] * rs1; o1.y = oc0[3] * rs1;
    *(float2*)(Obase + (size_t)qr0 * DD + dcol) = o0;
    *(float2*)(Obase + (size_t)qr1 * DD + dcol) = o1;
}

// ---------------- launch ----------------
extern "C" void kernel_launch(void* const* d_in, const int* in_sizes, int n_in,
                              void* d_out, int out_size) {
    const float* q_m  = (const float*)d_in[0];
    const float* q_c  = (const float*)d_in[1];
    const float* k_m  = (const float*)d_in[2];
    const float* k_c  = (const float*)d_in[3];
    const float* v_m  = (const float*)d_in[4];
    const float* v_c  = (const float*)d_in[5];
    const float* Wk_m = (const float*)d_in[6];
    const float* bk_m = (const float*)d_in[7];
    const float* Wk_c = (const float*)d_in[8];
    const float* bk_c = (const float*)d_in[9];
    const float* Wv_m = (const float*)d_in[10];
    const float* bv_m = (const float*)d_in[11];
    const float* Wv_c = (const float*)d_in[12];
    const float* bv_c = (const float*)d_in[13];
    const float* Wo_m = (const float*)d_in[14];
    const float* bo_m = (const float*)d_in[15];
    const float* Wo_c = (const float*)d_in[16];
    const float* bo_c = (const float*)d_in[17];
    const float* gam  = (const float*)d_in[18];
    float* out = (float*)d_out;

    float *bQ, *bK, *bV, *bO;
    cudaGetSymbolAddress((void**)&bQ, g_bufQ);
    cudaGetSymbolAddress((void**)&bK, g_bufK);
    cudaGetSymbolAddress((void**)&bV, g_bufV);
    cudaGetSymbolAddress((void**)&bO, g_bufO);

    cudaFuncSetAttribute(attn_kernel, cudaFuncAttributeMaxDynamicSharedMemorySize,
                         ATTN_SM_FLOATS * 4);

    // 6 projection GEMMs in one launch (Q and K share Wk per stream)
    GB8 proj{};
    proj.g[0] = { q_m, Wk_m, bk_m, bQ };
    proj.g[1] = { k_m, Wk_m, bk_m, bK };
    proj.g[2] = { v_m, Wv_m, bv_m, bV };
    proj.g[3] = { q_c, Wk_c, bk_c, bQ + BSD };
    proj.g[4] = { k_c, Wk_c, bk_c, bK + BSD };
    proj.g[5] = { v_c, Wv_c, bv_c, bV + BSD };
    gemm_tc_kernel<<<dim3(512 / 128, 4096 / 128, 6), 256>>>(proj);

    // attention (both streams) — heavy-first tile order, TQ=32
    attn_kernel<<<dim3(BB * HH, SS / TQ, 2), 512, ATTN_SM_FLOATS * 4>>>(gam);

    // 2 output GEMMs in one launch
    GB8 outp{};
    outp.g[0] = { bO,       Wo_m, bo_m, out };
    outp.g[1] = { bO + BSD, Wo_c, bo_c, out + BSD };
    gemm_tc_kernel<<<dim3(512 / 128, 4096 / 128, 2), 256>>>(outp);
}